// round 6
// baseline (speedup 1.0000x reference)
#include <cuda_runtime.h>

// db4 single-level 2D DWT, circular padding (end), stride-2 cross-correlation.
// x: (96, 512, 512) f32 -> out: (96*4, 256, 256) f32, subband order ll,lh,hl,hh.
//
// Warp-autonomous: each warp computes a 32(cols) x 16(rows) output tile with no
// shared memory and no barriers. Lane = output column. Row-pass windows are
// assembled via warp shuffles; column pass uses a register ring of 8 rows.

#define HH   512
#define WW   512
#define OWW  256

__global__ __launch_bounds__(256) void dwt2d_db4_kernel(
    const float* __restrict__ x,
    float* __restrict__ out)
{
    const float FL[8] = {-0.010597401784997278f,  0.032883011666982945f,
                          0.030841381835986965f, -0.18703481171888114f,
                         -0.02798376941698385f,   0.6308807679295904f,
                          0.7148465705525415f,    0.23037781330885523f};
    const float FH[8] = {-0.23037781330885523f,   0.7148465705525415f,
                         -0.6308807679295904f,   -0.02798376941698385f,
                          0.18703481171888114f,   0.030841381835986965f,
                         -0.032883011666982945f, -0.010597401784997278f};

    const int lane = threadIdx.x & 31;
    const int wt   = blockIdx.x * 8 + (threadIdx.x >> 5);  // warp-tile id, 0..12287
    const int img  = wt >> 7;            // 0..95
    const int rem  = wt & 127;
    const int ty   = rem >> 3;           // 0..15  (16-row output stripes)
    const int tx   = rem & 7;            // 0..7   (32-col output stripes)
    const int h0   = ty * 16;
    const int w0   = tx * 32;
    const int r0   = 2 * h0;
    const int c0   = 2 * w0;

    const float* __restrict__ xin  = x   + (size_t)img * HH * WW;
    float*       __restrict__ outi = out + (size_t)img * 4 * OWW * OWW;
    const size_t SB = (size_t)OWW * OWW;

    // lane's primary float2 column (never wraps: c0+62 <= 510)
    const int gc  = c0 + 2 * lane;
    // extra pairs for cols 64..69 (may wrap), held by lanes 0..2
    const int gcE = (c0 + 64 + 2 * lane) & (WW - 1);
    const bool hasE = (lane < 3);
    const unsigned FULL = 0xFFFFFFFFu;

    float rlo[8], rhi[8];

    // row pass for one input row -> (lo, hi) at this lane's output column
    auto rp = [&](int row, float& lo, float& hi) {
        int gr = (r0 + row) & (HH - 1);
        const float* __restrict__ rowp = xin + (size_t)gr * WW;
        float2 P = *(const float2*)(rowp + gc);
        float Ex = 0.f, Ey = 0.f;
        if (hasE) { float2 E = *(const float2*)(rowp + gcE); Ex = E.x; Ey = E.y; }
        float a1x = __shfl_down_sync(FULL, P.x, 1), a1y = __shfl_down_sync(FULL, P.y, 1);
        float a2x = __shfl_down_sync(FULL, P.x, 2), a2y = __shfl_down_sync(FULL, P.y, 2);
        float a3x = __shfl_down_sync(FULL, P.x, 3), a3y = __shfl_down_sync(FULL, P.y, 3);
        float E0x = __shfl_sync(FULL, Ex, 0), E0y = __shfl_sync(FULL, Ey, 0);
        float E1x = __shfl_sync(FULL, Ex, 1), E1y = __shfl_sync(FULL, Ey, 1);
        float E2x = __shfl_sync(FULL, Ex, 2), E2y = __shfl_sync(FULL, Ey, 2);
        if (lane == 29) {                                     a3x = E0x; a3y = E0y; }
        if (lane == 30) {           a2x = E0x; a2y = E0y;     a3x = E1x; a3y = E1y; }
        if (lane == 31) { a1x = E0x; a1y = E0y; a2x = E1x; a2y = E1y; a3x = E2x; a3y = E2y; }
        float l, h;
        l = FL[0] * P.x;            h = FH[0] * P.x;
        l = fmaf(FL[1], P.y, l);    h = fmaf(FH[1], P.y, h);
        l = fmaf(FL[2], a1x, l);    h = fmaf(FH[2], a1x, h);
        l = fmaf(FL[3], a1y, l);    h = fmaf(FH[3], a1y, h);
        l = fmaf(FL[4], a2x, l);    h = fmaf(FH[4], a2x, h);
        l = fmaf(FL[5], a2y, l);    h = fmaf(FH[5], a2y, h);
        l = fmaf(FL[6], a3x, l);    h = fmaf(FH[6], a3x, h);
        l = fmaf(FL[7], a3y, l);    h = fmaf(FH[7], a3y, h);
        lo = l; hi = h;
    };

    // preload row-pass rows 0..5 into ring slots 0..5
    rp(0, rlo[0], rhi[0]);
    rp(1, rlo[1], rhi[1]);
    rp(2, rlo[2], rhi[2]);
    rp(3, rlo[3], rhi[3]);
    rp(4, rlo[4], rhi[4]);
    rp(5, rlo[5], rhi[5]);

    // 16 output rows; ring slot pattern repeats with period 4 -> unroll inner only
    #pragma unroll 1
    for (int hb = 0; hb < 16; hb += 4) {
        #pragma unroll
        for (int u = 0; u < 4; u++) {
            int h = hb + u;
            rp(2 * h + 6, rlo[(2 * u + 6) & 7], rhi[(2 * u + 6) & 7]);
            rp(2 * h + 7, rlo[(2 * u + 7) & 7], rhi[(2 * u + 7) & 7]);
            float ll = 0.f, lh = 0.f, hl = 0.f, hh = 0.f;
            #pragma unroll
            for (int t = 0; t < 8; t++) {
                int s = (2 * u + t) & 7;
                ll = fmaf(FL[t], rlo[s], ll);  lh = fmaf(FH[t], rlo[s], lh);
                hl = fmaf(FL[t], rhi[s], hl);  hh = fmaf(FH[t], rhi[s], hh);
            }
            size_t o = (size_t)(h0 + h) * OWW + (w0 + lane);
            outi[0 * SB + o] = ll;
            outi[1 * SB + o] = lh;
            outi[2 * SB + o] = hl;
            outi[3 * SB + o] = hh;
        }
    }
}

extern "C" void kernel_launch(void* const* d_in, const int* in_sizes, int n_in,
                              void* d_out, int out_size)
{
    const float* x = (const float*)d_in[0];   // (32,3,512,512) f32
    float* out = (float*)d_out;               // (32,12,256,256) f32

    // 96 images x (16 x 8) warp tiles = 12288 warps; 8 warps per block
    dwt2d_db4_kernel<<<1536, 256>>>(x, out);
}

// round 8
// speedup vs baseline: 1.2396x; 1.2396x over previous
#include <cuda_runtime.h>

// db4 single-level 2D DWT, circular padding (end), stride-2 cross-correlation.
// x: (96, 512, 512) f32 -> out: (96*4, 256, 256) f32, subband order ll,lh,hl,hh.
//
// Two phases, one sync, forced 8 blocks/SM (32-reg target):
//   A) row pass straight from GMEM (coalesced float4/float2 windows) -> smem {lo,hi}
//   B) column pass from smem -> 4 subbands, coalesced stores.

#define HH   512
#define WW   512
#define OWW  256
#define TH   32            // output tile rows per block
#define TW   32            // output tile cols per block
#define IN_H 70            // row-pass rows needed (2*TH + 6)
#define LP   34            // s_lh pitch in float2

__global__ __launch_bounds__(256, 8) void dwt2d_db4_kernel(
    const float* __restrict__ x,
    float* __restrict__ out)
{
    __shared__ __align__(16) float2 s_lh[IN_H][LP];   // {lo,hi} per row-pass output col

    const float FL[8] = {-0.010597401784997278f,  0.032883011666982945f,
                          0.030841381835986965f, -0.18703481171888114f,
                         -0.02798376941698385f,   0.6308807679295904f,
                          0.7148465705525415f,    0.23037781330885523f};
    const float FH[8] = {-0.23037781330885523f,   0.7148465705525415f,
                         -0.6308807679295904f,   -0.02798376941698385f,
                          0.18703481171888114f,   0.030841381835986965f,
                         -0.032883011666982945f, -0.010597401784997278f};

    const int tid = threadIdx.x;
    const int img = blockIdx.z;             // 0..95
    const int h0  = blockIdx.y * TH;
    const int w0  = blockIdx.x * TW;
    const int r0  = 2 * h0;
    const int c0  = 2 * w0;                 // multiple of 64

    const float* __restrict__ xin = x + (size_t)img * HH * WW;

    // ---- phase A: row pass directly from GMEM ----
    // item = (r 0..69, c 0..15): outputs w = 2c, 2c+1 from input cols 4c .. 4c+9.
    // lanes are c-fast -> loads contiguous across half-warps.
    #pragma unroll
    for (int i = 0; i < 5; i++) {
        int idx = tid + i * 256;
        if (idx < IN_H * 16) {
            int r = idx >> 4;
            int c = idx & 15;
            int gr = (r0 + r) & (HH - 1);
            const float* __restrict__ rowp = xin + (size_t)gr * WW;
            int g0 = (c0 + 4 * c)     & (WW - 1);
            int g1 = (c0 + 4 * c + 4) & (WW - 1);
            int g2 = (c0 + 4 * c + 8) & (WW - 1);
            float4 q0 = *(const float4*)(rowp + g0);
            float4 q1 = *(const float4*)(rowp + g1);
            float2 q2 = *(const float2*)(rowp + g2);
            float v[10] = {q0.x, q0.y, q0.z, q0.w,
                           q1.x, q1.y, q1.z, q1.w,
                           q2.x, q2.y};
            float lo0 = 0.f, hi0 = 0.f, lo1 = 0.f, hi1 = 0.f;
            #pragma unroll
            for (int t = 0; t < 8; t++) {
                lo0 = fmaf(FL[t], v[t],     lo0);
                hi0 = fmaf(FH[t], v[t],     hi0);
                lo1 = fmaf(FL[t], v[t + 2], lo1);
                hi1 = fmaf(FH[t], v[t + 2], hi1);
            }
            *(float4*)&s_lh[r][2 * c] = make_float4(lo0, hi0, lo1, hi1);
        }
    }
    __syncthreads();

    // ---- phase B: column pass ----
    // item = (w 0..31, hp 0..15): 2 output rows (2hp, 2hp+1) x 1 col x 4 subbands.
    // lanes are w-fast -> LDS.64 and STG.32 fully coalesced.
    float* __restrict__ outi = out + (size_t)img * 4 * OWW * OWW;
    const int w   = tid & 31;
    const int hpb = tid >> 5;               // 0..7
    const size_t SB = (size_t)OWW * OWW;

    #pragma unroll
    for (int i = 0; i < 2; i++) {
        int hp = hpb + i * 8;               // 0..15
        float ll0 = 0.f, lh0 = 0.f, hl0 = 0.f, hh0 = 0.f;   // row 2hp
        float ll1 = 0.f, lh1 = 0.f, hl1 = 0.f, hh1 = 0.f;   // row 2hp+1
        #pragma unroll
        for (int t = 0; t < 10; t++) {
            float2 a = s_lh[4 * hp + t][w];
            if (t < 8) {
                ll0 = fmaf(FL[t], a.x, ll0);  lh0 = fmaf(FH[t], a.x, lh0);
                hl0 = fmaf(FL[t], a.y, hl0);  hh0 = fmaf(FH[t], a.y, hh0);
            }
            if (t >= 2) {
                ll1 = fmaf(FL[t - 2], a.x, ll1);  lh1 = fmaf(FH[t - 2], a.x, lh1);
                hl1 = fmaf(FL[t - 2], a.y, hl1);  hh1 = fmaf(FH[t - 2], a.y, hh1);
            }
        }
        size_t oA = (size_t)(h0 + 2 * hp)     * OWW + (w0 + w);
        size_t oB = (size_t)(h0 + 2 * hp + 1) * OWW + (w0 + w);
        outi[0 * SB + oA] = ll0;  outi[0 * SB + oB] = ll1;
        outi[1 * SB + oA] = lh0;  outi[1 * SB + oB] = lh1;
        outi[2 * SB + oA] = hl0;  outi[2 * SB + oB] = hl1;
        outi[3 * SB + oA] = hh0;  outi[3 * SB + oB] = hh1;
    }
}

extern "C" void kernel_launch(void* const* d_in, const int* in_sizes, int n_in,
                              void* d_out, int out_size)
{
    const float* x = (const float*)d_in[0];   // (32,3,512,512) f32
    float* out = (float*)d_out;               // (32,12,256,256) f32

    dim3 grid(OWW / TW, OWW / TH, 96);        // (8, 8, 96)
    dwt2d_db4_kernel<<<grid, 256>>>(x, out);
}

// round 9
// speedup vs baseline: 1.2904x; 1.0410x over previous
#include <cuda_runtime.h>

// db4 single-level 2D DWT, circular padding (end), stride-2 cross-correlation.
// x: (96, 512, 512) f32 -> out: (96*4, 256, 256) f32, subband order ll,lh,hl,hh.
//
// Column pass FIRST (full-width stripes, perfectly coalesced streaming loads,
// zero intermediate overproduction), then row pass from smem planes.

#define HH   512
#define WW   512
#define OWW  256
#define TH   8             // output rows per block (stripe height)
#define IN_R (2*TH + 6)    // 22 input rows per stripe
#define PW   520           // plane width: 512 + 8 wrap-halo cols (16B-multiple rows)

__global__ __launch_bounds__(512, 4) void dwt2d_db4_kernel(
    const float* __restrict__ x,
    float* __restrict__ out)
{
    __shared__ __align__(16) float s_lo[TH][PW];   // col-pass LO plane
    __shared__ __align__(16) float s_hi[TH][PW];   // col-pass HI plane

    const float FL[8] = {-0.010597401784997278f,  0.032883011666982945f,
                          0.030841381835986965f, -0.18703481171888114f,
                         -0.02798376941698385f,   0.6308807679295904f,
                          0.7148465705525415f,    0.23037781330885523f};
    const float FH[8] = {-0.23037781330885523f,   0.7148465705525415f,
                         -0.6308807679295904f,   -0.02798376941698385f,
                          0.18703481171888114f,   0.030841381835986965f,
                         -0.032883011666982945f, -0.010597401784997278f};

    const int tid = threadIdx.x;          // 0..511
    const int sy  = blockIdx.x;           // 0..31 stripe
    const int img = blockIdx.y;           // 0..95
    const int h0  = sy * TH;              // output row base
    const int r0  = 2 * h0;               // input row base

    const float* __restrict__ xin = x + (size_t)img * HH * WW;

    // ---- phase A: column pass, thread owns input column c = tid ----
    // Streams 22 rows (1 coalesced LDG.32 per row per thread), ring of 4
    // (lo,hi) accumulator pairs; output j retires at tap t==7.
    {
        const int c = tid;
        float alo[4], ahi[4];
        #pragma unroll
        for (int k = 0; k < IN_R; k++) {
            float v = xin[(size_t)((r0 + k) & (HH - 1)) * WW + c];
            #pragma unroll
            for (int j = 0; j < TH; j++) {
                const int t = k - 2 * j;
                if (t == 0) {
                    alo[j & 3] = FL[0] * v;
                    ahi[j & 3] = FH[0] * v;
                } else if (t > 0 && t < 8) {
                    alo[j & 3] = fmaf(FL[t], v, alo[j & 3]);
                    ahi[j & 3] = fmaf(FH[t], v, ahi[j & 3]);
                }
                if (t == 7) {
                    s_lo[j][c] = alo[j & 3];
                    s_hi[j][c] = ahi[j & 3];
                    if (c < 8) {                    // wrap halo for row pass
                        s_lo[j][WW + c] = alo[j & 3];
                        s_hi[j][WW + c] = ahi[j & 3];
                    }
                }
            }
        }
    }
    __syncthreads();

    // ---- phase B: row pass from smem planes ----
    // item = (plane, j, wp): output cols 2wp, 2wp+1 of output row h0+j.
    // plane lo -> ll (sb0) & hl (sb2); plane hi -> lh (sb1) & hh (sb3).
    float* __restrict__ outi = out + (size_t)img * 4 * OWW * OWW;
    const size_t SB = (size_t)OWW * OWW;

    #pragma unroll
    for (int it = 0; it < 4; it++) {
        int idx = tid + it * 512;            // 0..2047
        int wp  = idx & 127;                 // col-pair index
        int j   = (idx >> 7) & (TH - 1);     // 0..7
        int pl  = idx >> 10;                 // 0..1
        const float* __restrict__ A = pl ? &s_hi[j][0] : &s_lo[j][0];

        // window A[4wp .. 4wp+9]; reads are 16B-stride contiguous -> conflict-free
        float4 q0 = *(const float4*)(A + 4 * wp);
        float4 q1 = *(const float4*)(A + 4 * wp + 4);
        float4 q2 = *(const float4*)(A + 4 * wp + 8);   // only .x,.y used
        float v[10] = {q0.x, q0.y, q0.z, q0.w,
                       q1.x, q1.y, q1.z, q1.w,
                       q2.x, q2.y};

        float lo0 = 0.f, hi0 = 0.f, lo1 = 0.f, hi1 = 0.f;
        #pragma unroll
        for (int t = 0; t < 8; t++) {
            lo0 = fmaf(FL[t], v[t],     lo0);
            hi0 = fmaf(FH[t], v[t],     hi0);
            lo1 = fmaf(FL[t], v[t + 2], lo1);
            hi1 = fmaf(FH[t], v[t + 2], hi1);
        }

        int sbL = pl ? 1 : 0;    // row-lo result subband
        int sbH = pl ? 3 : 2;    // row-hi result subband
        size_t o = (size_t)(h0 + j) * OWW + 2 * wp;
        *(float2*)(outi + sbL * SB + o) = make_float2(lo0, lo1);
        *(float2*)(outi + sbH * SB + o) = make_float2(hi0, hi1);
    }
}

extern "C" void kernel_launch(void* const* d_in, const int* in_sizes, int n_in,
                              void* d_out, int out_size)
{
    const float* x = (const float*)d_in[0];   // (32,3,512,512) f32
    float* out = (float*)d_out;               // (32,12,256,256) f32

    dim3 grid(OWW / TH, 96);                  // (32 stripes, 96 images)
    dwt2d_db4_kernel<<<grid, 512>>>(x, out);
}